// round 9
// baseline (speedup 1.0000x reference)
#include <cuda_runtime.h>
#include <math.h>

#define BATCH 64
#define TT    256
#define EMBD  256
#define HH    1024
#define H3    3072

// Scratch (all __device__ bss — no allocation at runtime):
__device__ float      g_xw[2][TT * BATCH][H3];       // input projections, dir1 pre-time-reversed
__device__ ulonglong2 g_udup[2][64][512][48];        // U duplicated as f32x2 pairs: [dir][blk][k2][slot]
                                                     //  .x = (U[2k2][col],U[2k2][col])  .y = same for 2k2+1
__device__ unsigned int g_arrive[2];

// ---- f32x2 helpers (Blackwell packed fp32) --------------------------------
__device__ __forceinline__ unsigned long long pk2(float x, float y) {
    unsigned long long d;
    asm("mov.b64 %0, {%1, %2};" : "=l"(d) : "f"(x), "f"(y));
    return d;
}
__device__ __forceinline__ void upk2(unsigned long long d, float& x, float& y) {
    asm("mov.b64 {%0, %1}, %2;" : "=f"(x), "=f"(y) : "l"(d));
}
__device__ __forceinline__ void fma2(unsigned long long& d, unsigned long long a, unsigned long long b) {
    asm("fma.rn.f32x2 %0, %1, %2, %0;" : "+l"(d) : "l"(a), "l"(b));
}

// ---------------------------------------------------------------------------
// Kernel 0: build duplicated-U operand + reset grid-barrier counters.
// One thread per (dir, blk, k2, slot) element: 2*64*512*48 = 3,145,728.
// ---------------------------------------------------------------------------
__global__ void __launch_bounds__(256) udup_kernel(
    const float* __restrict__ Uf, const float* __restrict__ Ub)
{
    if (blockIdx.x == 0 && threadIdx.x == 0) { g_arrive[0] = 0u; g_arrive[1] = 0u; }

    long idx = (long)blockIdx.x * 256 + threadIdx.x;
    int slot = (int)(idx % 48);  long t1 = idx / 48;
    int k2   = (int)(t1 % 512);  long t2 = t1 / 512;
    int blk  = (int)(t2 % 64);   int dir = (int)(t2 / 64);
    if (dir > 1) return;

    const float* __restrict__ U = dir ? Ub : Uf;
    int g  = slot >> 4;
    int cl = slot & 15;
    int col = g * HH + blk * 16 + cl;
    float u0 = U[(size_t)(2 * k2) * H3 + col];
    float u1 = U[(size_t)(2 * k2 + 1) * H3 + col];
    ulonglong2 v;
    v.x = pk2(u0, u0);
    v.y = pk2(u1, u1);
    g_udup[dir][blk][k2][slot] = v;
}

// ---------------------------------------------------------------------------
// Kernel A: xw = gather(emb, x) @ W + b_input   (f32x2, row-pair packed)
// M=16384, N=3072, K=256. grid (256, 48, 2), 128 threads.
// ---------------------------------------------------------------------------
__global__ void __launch_bounds__(128) xw_gemm_kernel(
    const int* __restrict__ x,
    const float* __restrict__ emb,
    const float* __restrict__ Wf,
    const float* __restrict__ bf,
    const float* __restrict__ Wb,
    const float* __restrict__ bb)
{
    __shared__ float As[32][68];   // As[k][m]
    __shared__ float Bs[32][68];   // Bs[k][n]

    const int dir = blockIdx.z;
    const float* __restrict__ W    = dir ? Wb : Wf;
    const float* __restrict__ bias = dir ? bb : bf;   // row 0 = input bias

    const int m0  = blockIdx.x * 64;
    const int n0  = blockIdx.y * 64;
    const int tid = threadIdx.x;

    const int r0 = (tid >> 4) * 8;    // 8 output rows (4 row-pairs)
    const int c0 = (tid & 15) * 4;    // 4 output cols

    unsigned long long acc2[4][4] = {};   // [rowpair][col] packed (even,odd) rows

    for (int k0 = 0; k0 < EMBD; k0 += 32) {
        // ---- A tile fill (embedding gather) ----
        #pragma unroll
        for (int i = 0; i < 4; i++) {
            int q4 = i * 128 + tid;
            int m  = q4 >> 3;
            int k4 = q4 & 7;
            int n  = m0 + m;
            int s  = n >> 6;
            int b  = n & 63;
            int t  = dir ? (TT - 1 - s) : s;
            int tok = x[b * TT + t];
            float4 v = *(const float4*)(emb + (size_t)tok * EMBD + k0 + k4 * 4);
            As[k4 * 4 + 0][m] = v.x;
            As[k4 * 4 + 1][m] = v.y;
            As[k4 * 4 + 2][m] = v.z;
            As[k4 * 4 + 3][m] = v.w;
        }
        // ---- B tile fill ----
        #pragma unroll
        for (int i = 0; i < 4; i++) {
            int q4 = i * 128 + tid;
            int k  = q4 >> 4;
            int nf = q4 & 15;
            float4 v = *(const float4*)(W + (size_t)(k0 + k) * H3 + n0 + nf * 4);
            *(float4*)&Bs[k][nf * 4] = v;
        }
        __syncthreads();

        #pragma unroll
        for (int k = 0; k < 32; k++) {
            ulonglong2 a01 = *(const ulonglong2*)&As[k][r0];      // pairs (r0,r0+1),(r0+2,r0+3)
            ulonglong2 a23 = *(const ulonglong2*)&As[k][r0 + 4];  // pairs (r0+4,r0+5),(r0+6,r0+7)
            float4 bv = *(const float4*)&Bs[k][c0];
            unsigned long long b0 = pk2(bv.x, bv.x);
            unsigned long long b1 = pk2(bv.y, bv.y);
            unsigned long long b2 = pk2(bv.z, bv.z);
            unsigned long long b3 = pk2(bv.w, bv.w);
            fma2(acc2[0][0], a01.x, b0); fma2(acc2[0][1], a01.x, b1);
            fma2(acc2[0][2], a01.x, b2); fma2(acc2[0][3], a01.x, b3);
            fma2(acc2[1][0], a01.y, b0); fma2(acc2[1][1], a01.y, b1);
            fma2(acc2[1][2], a01.y, b2); fma2(acc2[1][3], a01.y, b3);
            fma2(acc2[2][0], a23.x, b0); fma2(acc2[2][1], a23.x, b1);
            fma2(acc2[2][2], a23.x, b2); fma2(acc2[2][3], a23.x, b3);
            fma2(acc2[3][0], a23.y, b0); fma2(acc2[3][1], a23.y, b1);
            fma2(acc2[3][2], a23.y, b2); fma2(acc2[3][3], a23.y, b3);
        }
        __syncthreads();
    }

    // ---- store + input bias ----
    const int j = n0 + c0;
    float4 bi = *(const float4*)(bias + j);
    #pragma unroll
    for (int p = 0; p < 4; p++) {
        float lo[4], hi[4];
        #pragma unroll
        for (int jj = 0; jj < 4; jj++) upk2(acc2[p][jj], lo[jj], hi[jj]);
        int row = m0 + r0 + 2 * p;
        float4 olo = { lo[0] + bi.x, lo[1] + bi.y, lo[2] + bi.z, lo[3] + bi.w };
        float4 ohi = { hi[0] + bi.x, hi[1] + bi.y, hi[2] + bi.z, hi[3] + bi.w };
        *(float4*)&g_xw[dir][row][j]     = olo;
        *(float4*)&g_xw[dir][row + 1][j] = ohi;
    }
}

// ---------------------------------------------------------------------------
// Kernel B: persistent bidirectional GRU scan (f32x2, reg-staged double buffer).
// 128 blocks (64/dir), 256 threads. Block owns 16 h-cols.
// ---------------------------------------------------------------------------
__global__ void __launch_bounds__(256, 1) gru_scan_kernel(
    const float* __restrict__ hidden,
    const float* __restrict__ bf,
    const float* __restrict__ bb,
    float* __restrict__ out)
{
    __shared__ float      As[64][68];     // h tile [b][k_local]
    __shared__ ulonglong2 Bsd[32][48];    // dup'd U tile [k2_local][slot]

    const int blk = blockIdx.x;
    const int dir = blk >> 6;
    const int cb  = (blk & 63) * 16;

    const float* __restrict__ brow = (dir ? bb : bf) + H3;  // recurrent bias

    const int tid = threadIdx.x;
    const int cl  = tid & 15;
    const int rg  = tid >> 4;           // 0..15
    const int r0  = rg * 4;             // 4 batch rows
    const int c   = cb + cl;

    const float bz_b = brow[c];
    const float br_b = brow[c + HH];
    const float bh_b = brow[c + 2 * HH];

    const float* __restrict__ xwbase = &g_xw[dir][0][0];
    const ulonglong2* __restrict__ ud = &g_udup[dir][blk & 63][0][0];
    const unsigned nb = 64;

    for (int s = 0; s < TT; s++) {
        // h source for this step: h(b) = hbase + b*hstride
        const float* hbase;
        size_t hstride;
        if (s == 0)          { hbase = hidden;                                hstride = HH; }
        else if (dir == 0)   { hbase = out + (size_t)(s - 1) * 2048;          hstride = (size_t)TT * 2048; }
        else                 { hbase = out + (size_t)(TT - s) * 2048 + HH;    hstride = (size_t)TT * 2048; }

        unsigned long long az01 = 0, az23 = 0, ar01 = 0, ar23 = 0, ah01 = 0, ah23 = 0;

        float4     ra[4];
        ulonglong2 rb[6];

        // prologue prefetch: tile 0
        #pragma unroll
        for (int i = 0; i < 4; i++) {
            int q = i * 256 + tid;
            int b = q >> 4, k4 = q & 15;
            ra[i] = __ldcg((const float4*)(hbase + (size_t)b * hstride + k4 * 4));
        }
        #pragma unroll
        for (int j = 0; j < 6; j++) rb[j] = ud[j * 256 + tid];

        for (int t = 0; t < 16; t++) {
            __syncthreads();              // previous tile fully consumed
            // store staged regs to smem
            #pragma unroll
            for (int i = 0; i < 4; i++) {
                int q = i * 256 + tid;
                int b = q >> 4, k4 = q & 15;
                *(float4*)&As[b][k4 * 4] = ra[i];
            }
            #pragma unroll
            for (int j = 0; j < 6; j++) ((ulonglong2*)Bsd)[j * 256 + tid] = rb[j];

            // prefetch next tile while computing this one
            if (t < 15) {
                #pragma unroll
                for (int i = 0; i < 4; i++) {
                    int q = i * 256 + tid;
                    int b = q >> 4, k4 = q & 15;
                    ra[i] = __ldcg((const float4*)(hbase + (size_t)b * hstride + (t + 1) * 64 + k4 * 4));
                }
                const ulonglong2* src = ud + (t + 1) * (32 * 48);
                #pragma unroll
                for (int j = 0; j < 6; j++) rb[j] = src[j * 256 + tid];
            }
            __syncthreads();              // tile ready

            #pragma unroll 8
            for (int k2 = 0; k2 < 32; k2++) {
                int kk = 2 * k2;
                float2 a0 = *(const float2*)&As[r0 + 0][kk];
                float2 a1 = *(const float2*)&As[r0 + 1][kk];
                float2 a2 = *(const float2*)&As[r0 + 2][kk];
                float2 a3 = *(const float2*)&As[r0 + 3][kk];
                ulonglong2 bz = Bsd[k2][cl];
                ulonglong2 br = Bsd[k2][16 + cl];
                ulonglong2 bh = Bsd[k2][32 + cl];
                unsigned long long a01k0 = pk2(a0.x, a1.x);
                unsigned long long a23k0 = pk2(a2.x, a3.x);
                unsigned long long a01k1 = pk2(a0.y, a1.y);
                unsigned long long a23k1 = pk2(a2.y, a3.y);
                fma2(az01, a01k0, bz.x); fma2(az01, a01k1, bz.y);
                fma2(az23, a23k0, bz.x); fma2(az23, a23k1, bz.y);
                fma2(ar01, a01k0, br.x); fma2(ar01, a01k1, br.y);
                fma2(ar23, a23k0, br.x); fma2(ar23, a23k1, br.y);
                fma2(ah01, a01k0, bh.x); fma2(ah01, a01k1, bh.y);
                fma2(ah23, a23k0, bh.x); fma2(ah23, a23k1, bh.y);
            }
        }

        // ---- gates + state update (4 rows) ----
        float vz[4], vr[4], vh[4];
        upk2(az01, vz[0], vz[1]); upk2(az23, vz[2], vz[3]);
        upk2(ar01, vr[0], vr[1]); upk2(ar23, vr[2], vr[3]);
        upk2(ah01, vh[0], vh[1]); upk2(ah23, vh[2], vh[3]);

        const size_t xrow = (size_t)s * BATCH;
        const int time = dir ? (TT - 1 - s) : s;
        #pragma unroll
        for (int jj = 0; jj < 4; jj++) {
            int b = r0 + jj;
            const float* xw = xwbase + (xrow + b) * H3;
            float xz = xw[c];
            float xr = xw[c + HH];
            float xh = xw[c + 2 * HH];
            float hprev = __ldcg(hbase + (size_t)b * hstride + c);

            float z    = 1.f / (1.f + expf(-(xz + vz[jj] + bz_b)));
            float r    = 1.f / (1.f + expf(-(xr + vr[jj] + br_b)));
            float cand = tanhf(xh + r * (vh[jj] + bh_b));
            float hn   = z * hprev + (1.f - z) * cand;

            out[((size_t)b * TT + time) * 2048 + dir * HH + c] = hn;
            if (s == TT - 1) {
                out[(size_t)BATCH * TT * 2048 + (size_t)dir * BATCH * HH + (size_t)b * HH + c] = hn;
            }
        }

        // ---- per-direction grid barrier ----
        if (s < TT - 1) {
            __syncthreads();
            if (tid == 0) {
                __threadfence();
                atomicAdd(&g_arrive[dir], 1u);
                unsigned target = nb * (unsigned)(s + 1);
                while (*(volatile unsigned*)&g_arrive[dir] < target) {
                    __nanosleep(32);
                }
            }
            __syncthreads();
        }
    }
}

// ---------------------------------------------------------------------------
extern "C" void kernel_launch(void* const* d_in, const int* in_sizes, int n_in,
                              void* d_out, int out_size)
{
    const int*   x      = (const int*)  d_in[0];
    const float* hidden = (const float*)d_in[1];
    const float* emb    = (const float*)d_in[2];
    const float* Wf     = (const float*)d_in[3];
    const float* Uf     = (const float*)d_in[4];
    const float* bf     = (const float*)d_in[5];
    const float* Wb     = (const float*)d_in[6];
    const float* Ub     = (const float*)d_in[7];
    const float* bb     = (const float*)d_in[8];
    float* out = (float*)d_out;

    udup_kernel<<<12288, 256>>>(Uf, Ub);
    dim3 ga(256, 48, 2);
    xw_gemm_kernel<<<ga, 128>>>(x, emb, Wf, bf, Wb, bb);
    gru_scan_kernel<<<128, 256>>>(hidden, bf, bb, out);
}